// round 11
// baseline (speedup 1.0000x reference)
#include <cuda_runtime.h>

// Problem constants (fixed shapes per reference setup_inputs)
#define SS 512
#define DD 2640
#define MM 64
// Only batch 7 contributes. Final scale = 1/(S*(S-1)) / M / (B*100)
// mask_list is int32 on device (JAX x64 disabled downcasts jnp.int64).
//
// Norm expansion with folded norms:
//   g_part[z][m][s] = -(r.i)_z + 0.5*||r_m||^2_z + 0.5*||i_s||^2_z
//   => sq(m,s) = 2 * sum_z g_part[z][m][s]

// Kernel A tiling: grid (4 s-tiles, 66 d-splits) = 264 CTAs, 256 threads.
#define ND    66      // d splits
#define DPC   40      // d per CTA
#define CHQ   10      // float4 (d-quads) per row
#define ROWS  192     // 64 target rows + 128 input rows
#define R4    193     // padded row stride in float4 units
#define STILE 128     // s per CTA
#define NELEM (ROWS * CHQ)

#define NB    512     // kB CTAs: 64 m x 8 s-chunks

__device__ float g_part[ND * MM * SS];   // folded partials: 8.65 MB
__device__ float g_pred[NB];
__device__ int   g_ticket = 0;

// ---------------------------------------------------------------------------
// Kernel A: folded partials, f32x2-packed (unchanged).
// ---------------------------------------------------------------------------
__global__ __launch_bounds__(256, 2) void kA(const float* __restrict__ input,
                                             const int* __restrict__ mask,
                                             const float* __restrict__ target)
{
    __shared__ __align__(16) float4 trp[CHQ * R4];   // 30880 B
    __shared__ const float* rowptr[ROWS];
    __shared__ float hn_r[MM];     // 0.5 * ||r_m||^2 partial (this z)
    __shared__ float hn_i[STILE];  // 0.5 * ||i_s||^2 partial (this z)

    const int tid  = threadIdx.x;
    const int lane = tid & 31;
    const int wid  = tid >> 5;
    const int sbase = blockIdx.x * STILE;
    const int dbase = blockIdx.y * DPC;

    if (tid < MM) {
        int im = mask[7 * MM + tid];
        rowptr[tid] = target + ((size_t)7 * SS + (size_t)im) * DD + dbase;
    } else if (tid < ROWS) {
        rowptr[tid] = input + ((size_t)7 * SS + (size_t)(sbase + tid - MM)) * DD + dbase;
    }
    __syncthreads();

    #pragma unroll
    for (int k = 0; k < 8; ++k) {
        int i = tid + k * 256;
        if (i < NELEM) {
            int row = i / CHQ, c = i - row * CHQ;
            float4 v = *(reinterpret_cast<const float4*>(rowptr[row]) + c);
            if (row >= MM) { v.x = -v.x; v.y = -v.y; v.z = -v.z; v.w = -v.w; }
            trp[c * R4 + row] = v;
        }
    }
    __syncthreads();

    if (tid < ROWS) {
        float ns = 0.0f;
        #pragma unroll
        for (int c = 0; c < CHQ; ++c) {
            float4 v = trp[c * R4 + tid];
            ns += v.x * v.x + v.y * v.y + v.z * v.z + v.w * v.w;
        }
        if (tid < MM) hn_r[tid] = 0.5f * ns;
        else          hn_i[tid - MM] = 0.5f * ns;
    }

    unsigned long long acc[32];
    #pragma unroll
    for (int i = 0; i < 32; ++i) acc[i] = 0ull;

    #pragma unroll 2
    for (int q = 0; q < CHQ; ++q) {
        const float4* base = trp + q * R4;
        ulonglong2 iv[4];
        #pragma unroll
        for (int b = 0; b < 4; ++b)
            iv[b] = *reinterpret_cast<const ulonglong2*>(base + MM + lane + 32 * b);
        #pragma unroll
        for (int a = 0; a < 8; ++a) {
            ulonglong2 rv = *reinterpret_cast<const ulonglong2*>(base + 8 * wid + a);
            #pragma unroll
            for (int b = 0; b < 4; ++b) {
                asm("fma.rn.f32x2 %0, %1, %2, %0;"
                    : "+l"(acc[a * 4 + b]) : "l"(rv.x), "l"(iv[b].x));
                asm("fma.rn.f32x2 %0, %1, %2, %0;"
                    : "+l"(acc[a * 4 + b]) : "l"(rv.y), "l"(iv[b].y));
            }
        }
    }
    __syncthreads();

    float* outp = g_part + (size_t)blockIdx.y * (MM * SS) + sbase;
    #pragma unroll
    for (int a = 0; a < 8; ++a) {
        int m = 8 * wid + a;
        float hr = hn_r[m];
        #pragma unroll
        for (int b = 0; b < 4; ++b) {
            unsigned long long v = acc[a * 4 + b];
            float lo = __uint_as_float((unsigned)(v & 0xffffffffu));
            float hi = __uint_as_float((unsigned)(v >> 32));
            int sl = lane + 32 * b;
            outp[(size_t)m * SS + sl] = (lo + hi) + hr + hn_i[sl];
        }
    }
}

// ---------------------------------------------------------------------------
// Kernel B: z-reduction split across lanes, loads via cp.async (LDGSTS) so
// MLP=9 is guaranteed by hardware, not by ptxas register allocation.
// Grid: 512 CTAs = (m = blockIdx&63, schunk = blockIdx>>6 of 64 s).
// 128 threads: tid = s4*8 + zc. zc handles z = zc + 8k (k<8) plus z = zc+64
// for zc<2. Each thread cp.asyncs its 8-9 float4s into its own smem column,
// waits its own group, reads back (no block barrier needed), shfl-folds the
// zc group, lane zc==0 applies the hinge. Deterministic ticket finish.
// ---------------------------------------------------------------------------
__global__ __launch_bounds__(128) void kB(const int* __restrict__ mask,
                                          float* __restrict__ out)
{
    __shared__ __align__(16) float4 sm[9 * 128];   // 18432 B

    const int m      = blockIdx.x & 63;
    const int schunk = blockIdx.x >> 6;      // 0..7
    const int tid    = threadIdx.x;
    const int s4     = tid >> 3;             // 0..15 (float4 group within chunk)
    const int zc     = tid & 7;              // 0..7  (z split)
    const int im     = mask[7 * MM + m];

    const size_t zs = (size_t)MM * SS / 4;   // z-stride in float4
    const float4* p = reinterpret_cast<const float4*>(g_part)
                    + (size_t)m * (SS / 4) + schunk * 16 + s4 + (size_t)zc * zs;

    unsigned smb = (unsigned)__cvta_generic_to_shared(&sm[tid]);
    #pragma unroll
    for (int k = 0; k < 8; ++k) {   // z = zc + 8k
        asm volatile("cp.async.ca.shared.global [%0], [%1], 16;"
                     :: "r"(smb + k * 128 * 16), "l"(p + (size_t)(8 * k) * zs));
    }
    if (zc < 2) {                    // z = zc + 64
        asm volatile("cp.async.ca.shared.global [%0], [%1], 16;"
                     :: "r"(smb + 8 * 128 * 16), "l"(p + (size_t)64 * zs));
    }
    asm volatile("cp.async.commit_group;");
    asm volatile("cp.async.wait_group 0;" ::: "memory");

    float4 v[8];
    #pragma unroll
    for (int k = 0; k < 8; ++k) v[k] = sm[k * 128 + tid];
    float4 v8 = make_float4(0.f, 0.f, 0.f, 0.f);
    if (zc < 2) v8 = sm[8 * 128 + tid];

    float4 t;
    t.x = (((v[0].x + v[1].x) + (v[2].x + v[3].x)) + ((v[4].x + v[5].x) + (v[6].x + v[7].x))) + v8.x;
    t.y = (((v[0].y + v[1].y) + (v[2].y + v[3].y)) + ((v[4].y + v[5].y) + (v[6].y + v[7].y))) + v8.y;
    t.z = (((v[0].z + v[1].z) + (v[2].z + v[3].z)) + ((v[4].z + v[5].z) + (v[6].z + v[7].z))) + v8.z;
    t.w = (((v[0].w + v[1].w) + (v[2].w + v[3].w)) + ((v[4].w + v[5].w) + (v[6].w + v[7].w))) + v8.w;

    // fold the 8-lane zc group (xor butterfly stays within the group)
    #pragma unroll
    for (int o = 4; o >= 1; o >>= 1) {
        t.x += __shfl_xor_sync(0xffffffffu, t.x, o);
        t.y += __shfl_xor_sync(0xffffffffu, t.y, o);
        t.z += __shfl_xor_sync(0xffffffffu, t.z, o);
        t.w += __shfl_xor_sync(0xffffffffu, t.w, o);
    }

    float val = 0.0f;
    if (zc == 0) {
        const int s0 = schunk * 64 + s4 * 4;
        const float* c = &t.x;
        #pragma unroll
        for (int j = 0; j < 4; ++j) {
            float sq = 2.0f * c[j];
            int d = im - (s0 + j);
            if (d < 0) d = -d;
            val += (d <= 1) ? sq : fmaxf(0.0f, 15000.0f - sq);
        }
    }

    // block reduce
    __shared__ float red[4];
    #pragma unroll
    for (int o = 16; o >= 1; o >>= 1)
        val += __shfl_down_sync(0xffffffffu, val, o);
    if ((tid & 31) == 0) red[tid >> 5] = val;
    __syncthreads();
    if (tid == 0) g_pred[blockIdx.x] = (red[0] + red[1]) + (red[2] + red[3]);

    // last-block final reduce (deterministic fixed-order partial sums)
    __shared__ int is_last;
    __threadfence();
    if (tid == 0) is_last = (atomicAdd(&g_ticket, 1) == NB - 1);
    __syncthreads();
    if (is_last) {
        __threadfence();
        float t2 = 0.0f;
        #pragma unroll
        for (int i = 0; i < NB / 128; ++i) t2 += g_pred[tid + i * 128];
        #pragma unroll
        for (int o = 16; o >= 1; o >>= 1)
            t2 += __shfl_down_sync(0xffffffffu, t2, o);
        if ((tid & 31) == 0) red[tid >> 5] = t2;
        __syncthreads();
        if (tid == 0) {
            const float scale = (float)(1.0 / (261632.0 * 64.0 * 800.0)); // 1/(S(S-1))/M/(B*100)
            out[0] = ((red[0] + red[1]) + (red[2] + red[3])) * scale;
            g_ticket = 0;   // reset for next graph replay
        }
    }
}

// ---------------------------------------------------------------------------
extern "C" void kernel_launch(void* const* d_in, const int* in_sizes, int n_in,
                              void* d_out, int out_size)
{
    const float* input  = (const float*)d_in[0];
    const int*   mask   = (const int*)d_in[1];
    const float* target = (const float*)d_in[2];
    float*       out    = (float*)d_out;

    kA<<<dim3(4, ND), 256>>>(input, mask, target);
    kB<<<NB, 128>>>(mask, out);
}